// round 5
// baseline (speedup 1.0000x reference)
#include <cuda_runtime.h>
#include <math.h>

#define Nn 20000
#define Ee 320000
#define ET (Ee + Nn)
#define Bb 128
#define IN_F 25
#define D 64
#define HD 8
#define HDD (HD * D) /* 512 */

// ---------------- scratch (static device globals; no allocation) ----------------
__device__ float g_xh[Nn * HDD];        // 41 MB
__device__ float g_as[Nn * HD];
__device__ float g_ad[Nn * HD];
__device__ int   g_cnt[Nn];
__device__ int   g_off[Nn + 1];
__device__ int   g_cur[Nn];
__device__ int   g_esrc[ET];
__device__ float g_agg[Nn * HDD];       // 41 MB
__device__ float g_outF[Nn * D];        // 5.1 MB
__device__ int   g_gstart[Bb];
__device__ int   g_gcnt[Bb];
__device__ float g_w2[Nn];
// index dtype handling
__device__ int   g_is64;
__device__ int   g_eidx[2 * Ee];
__device__ int   g_bat[Nn];

__device__ __forceinline__ float sigf(float x) { return 1.0f / (1.0f + __expf(-x)); }

// ---- packed fp32x2 helpers (Blackwell double-rate fp32) ----
__device__ __forceinline__ unsigned long long pk2(float lo, float hi) {
    unsigned long long r;
    asm("mov.b64 %0, {%1,%2};" : "=l"(r) : "f"(lo), "f"(hi));
    return r;
}
__device__ __forceinline__ void upk2(unsigned long long v, float& lo, float& hi) {
    asm("mov.b64 {%0,%1}, %2;" : "=f"(lo), "=f"(hi) : "l"(v));
}
__device__ __forceinline__ void fma2(unsigned long long& acc, unsigned long long a,
                                     unsigned long long b) {
    asm("fma.rn.f32x2 %0, %1, %2, %0;" : "+l"(acc) : "l"(a), "l"(b));
}

// ---------------- dtype probe: int64 values in [0,20000) have hi word == 0 ------
__global__ void k_detect(const void* __restrict__ ei) {
    if (threadIdx.x == 0) {
        const int2* p = (const int2*)ei;
        int ok64 = 1;
        for (int j = 0; j < 64; j++) if (p[j].y != 0) ok64 = 0;
        g_is64 = ok64;
    }
}

__global__ void k_cvt(const void* __restrict__ ei, const void* __restrict__ bat) {
    int i = blockIdx.x * blockDim.x + threadIdx.x;
    int is64 = g_is64;
    if (i < 2 * Ee)
        g_eidx[i] = is64 ? (int)((const long long*)ei)[i] : ((const int*)ei)[i];
    if (i < Nn)
        g_bat[i] = is64 ? (int)((const long long*)bat)[i] : ((const int*)bat)[i];
}

__global__ void k_init() {
    int i = blockIdx.x * blockDim.x + threadIdx.x;
    if (i < Nn) g_cnt[i] = 0;
    if (i < Bb) { g_gstart[i] = Nn; g_gcnt[i] = 0; }
}

// ---------------- fused: h0 = relu(x@W0+b0); xh = h0 @ Wg  (32 rows/block) ------
__global__ void k_xh(const float* __restrict__ x, const float* __restrict__ W0,
                     const float* __restrict__ b0, const float* __restrict__ Wg) {
    __shared__ float sx[32 * IN_F];
    __shared__ float sW[IN_F * D];
    __shared__ __align__(8) float2 sh0[64 * 17];   // [k][rowpair], pad 17
    int tid = threadIdx.x;  // 256
    int r0 = blockIdx.x * 32;
    for (int i = tid; i < 32 * IN_F; i += 256) sx[i] = x[r0 * IN_F + i];
    for (int i = tid; i < IN_F * D; i += 256) sW[i] = W0[i];
    __syncthreads();
    // phase A: h0 tile (32 x 64), stored transposed as row-pairs
    {
        int cc = tid & 63, g = tid >> 6;   // g in 0..3, rows 8g..8g+7
        float bb = b0[cc];
#pragma unroll
        for (int rp = 0; rp < 4; rp++) {
            int rr = g * 8 + rp * 2;
            float a0 = bb, a1 = bb;
#pragma unroll
            for (int k = 0; k < IN_F; k++) {
                float w = sW[k * 64 + cc];
                a0 = fmaf(sx[rr * IN_F + k], w, a0);
                a1 = fmaf(sx[(rr + 1) * IN_F + k], w, a1);
            }
            sh0[cc * 17 + g * 4 + rp] = make_float2(fmaxf(a0, 0.f), fmaxf(a1, 0.f));
        }
    }
    __syncthreads();
    // phase B: 32x512 GEMM, packed fp32x2 over row pairs, 2 cols/thread
    const unsigned long long* sh0u = (const unsigned long long*)sh0;
    int c = tid;
    unsigned long long acc0[16], acc1[16];
#pragma unroll
    for (int rp = 0; rp < 16; rp++) { acc0[rp] = 0ULL; acc1[rp] = 0ULL; }
    for (int k = 0; k < 64; k++) {
        float w0 = Wg[k * HDD + c];
        float w1 = Wg[k * HDD + 256 + c];
        unsigned long long wp0 = pk2(w0, w0), wp1 = pk2(w1, w1);
        const unsigned long long* row = sh0u + k * 17;
#pragma unroll
        for (int rp = 0; rp < 16; rp++) {
            unsigned long long a = row[rp];
            fma2(acc0[rp], a, wp0);
            fma2(acc1[rp], a, wp1);
        }
    }
    float* op = g_xh + (size_t)r0 * HDD + c;
#pragma unroll
    for (int rp = 0; rp < 16; rp++) {
        float lo, hi;
        upk2(acc0[rp], lo, hi);
        op[(2 * rp) * HDD] = lo;
        op[(2 * rp + 1) * HDD] = hi;
        upk2(acc1[rp], lo, hi);
        op[(2 * rp) * HDD + 256] = lo;
        op[(2 * rp + 1) * HDD + 256] = hi;
    }
}

// ---------------- a_s, a_d ------------------------------------------------------
__global__ void k_att(const float* __restrict__ att_src, const float* __restrict__ att_dst) {
    int i = blockIdx.x * blockDim.x + threadIdx.x;  // i = n*8 + h
    if (i >= Nn * HD) return;
    int h = i & 7;
    const float4* xr = (const float4*)(g_xh + (size_t)i * D);
    const float4* a4 = (const float4*)(att_src + h * D);
    const float4* b4 = (const float4*)(att_dst + h * D);
    float s = 0.f, d = 0.f;
#pragma unroll
    for (int j = 0; j < 16; j++) {
        float4 v = xr[j], a = a4[j], b = b4[j];
        s += v.x * a.x + v.y * a.y + v.z * a.z + v.w * a.w;
        d += v.x * b.x + v.y * b.y + v.z * b.z + v.w * b.w;
    }
    g_as[i] = s;
    g_ad[i] = d;
}

// ---------------- CSR build -----------------------------------------------------
__global__ void k_hist() {
    int e = blockIdx.x * blockDim.x + threadIdx.x;
    if (e < ET) {
        int dst = (e < Ee) ? g_eidx[Ee + e] : (e - Ee);
        atomicAdd(&g_cnt[dst], 1);
    }
    if (e < Nn) {
        int b = g_bat[e];
        atomicMin(&g_gstart[b], e);
        atomicAdd(&g_gcnt[b], 1);
    }
}

// single-block register-chunk scan: 2 barriers total
__global__ void k_scan() {
    __shared__ int warpsum[32];
    int tid = threadIdx.x;  // 1024
    const int CH = 20;      // 1024*20 >= 20000
    int base = tid * CH;
    int v[CH];
    int tot = 0;
#pragma unroll
    for (int i = 0; i < CH; i++) {
        int idx = base + i;
        int t = (idx < Nn) ? g_cnt[idx] : 0;
        v[i] = tot;
        tot += t;
    }
    int lane = tid & 31, wid = tid >> 5;
    int sc = tot;
#pragma unroll
    for (int o = 1; o < 32; o <<= 1) {
        int t = __shfl_up_sync(0xffffffff, sc, o);
        if (lane >= o) sc += t;
    }
    if (lane == 31) warpsum[wid] = sc;
    __syncthreads();
    if (wid == 0) {
        int s = warpsum[lane];
#pragma unroll
        for (int o = 1; o < 32; o <<= 1) {
            int t = __shfl_up_sync(0xffffffff, s, o);
            if (lane >= o) s += t;
        }
        warpsum[lane] = s;
    }
    __syncthreads();
    int basesum = sc - tot + (wid ? warpsum[wid - 1] : 0);
#pragma unroll
    for (int i = 0; i < CH; i++) {
        int idx = base + i;
        if (idx < Nn) {
            int e = basesum + v[i];
            g_off[idx] = e;
            g_cur[idx] = e;
        }
    }
    if (tid == 1023) g_off[Nn] = basesum + tot;
}

__global__ void k_scatter() {
    int e = blockIdx.x * blockDim.x + threadIdx.x;
    if (e >= ET) return;
    int src, dst;
    if (e < Ee) { src = g_eidx[e]; dst = g_eidx[Ee + e]; }
    else        { src = e - Ee;    dst = src; }
    int p = atomicAdd(&g_cur[dst], 1);
    g_esrc[p] = src;
}

// ---------------- fused per-dst segment softmax + aggregation -------------------
#define FMA4(A, R) { A.x += w * R.x; A.y += w * R.y; A.z += w * R.z; A.w += w * R.w; }
__global__ void k_agg() {
    int warp = (blockIdx.x * blockDim.x + threadIdx.x) >> 5;
    int lane = threadIdx.x & 31;
    if (warp >= Nn) return;
    int v = warp;
    int beg = g_off[v], end = g_off[v + 1];
    int h = lane >> 2;
    float adh = g_ad[v * HD + h];

    float mx = -1e30f;
    for (int i = beg; i < end; i++) {
        int s = g_esrc[i];
        float e = g_as[s * HD + h] + adh;
        e = (e > 0.f) ? e : 0.2f * e;
        mx = fmaxf(mx, e);
    }
    float ssum = 0.f;
    float4 a0 = {0, 0, 0, 0}, a1 = {0, 0, 0, 0}, a2 = {0, 0, 0, 0}, a3 = {0, 0, 0, 0};
    for (int i = beg; i < end; i++) {
        int s = g_esrc[i];
        float e = g_as[s * HD + h] + adh;
        e = (e > 0.f) ? e : 0.2f * e;
        float w = __expf(e - mx);
        ssum += w;
        const float4* row = (const float4*)(g_xh + (size_t)s * HDD) + lane * 4;
        float4 r0 = row[0], r1 = row[1], r2 = row[2], r3 = row[3];
        FMA4(a0, r0); FMA4(a1, r1); FMA4(a2, r2); FMA4(a3, r3);
    }
    float inv = 1.f / ssum;
    float4* o = (float4*)(g_agg + (size_t)v * HDD) + lane * 4;
    o[0] = make_float4(a0.x * inv, a0.y * inv, a0.z * inv, a0.w * inv);
    o[1] = make_float4(a1.x * inv, a1.y * inv, a1.z * inv, a1.w * inv);
    o[2] = make_float4(a2.x * inv, a2.y * inv, a2.z * inv, a2.w * inv);
    o[3] = make_float4(a3.x * inv, a3.y * inv, a3.z * inv, a3.w * inv);
}

// ---------------- out = relu(relu(agg + bg) @ Wh + bh) (16 rows/block, f32x2) ---
__global__ void k_out(const float* __restrict__ bg, const float* __restrict__ Wh,
                      const float* __restrict__ bh) {
    __shared__ __align__(8) float sAf[512 * 9 * 2];  // [k][rp(8)+pad] float2 -> 36.9KB
    int tid = threadIdx.x;  // 256
    int r0 = blockIdx.x * 16;
    for (int i = tid; i < 16 * 512; i += 256) {
        int r = i >> 9, k = i & 511;
        float a = fmaxf(g_agg[(size_t)(r0 + r) * HDD + k] + bg[k], 0.f);
        sAf[(k * 9 + (r >> 1)) * 2 + (r & 1)] = a;
    }
    __syncthreads();
    int c = tid & 63, g = tid >> 6;  // group g handles rowpairs 2g, 2g+1
    const unsigned long long* sA = (const unsigned long long*)sAf;
    unsigned long long acc0 = 0ULL, acc1 = 0ULL;
#pragma unroll 4
    for (int k = 0; k < 512; k++) {
        float w = Wh[k * 64 + c];
        unsigned long long wp = pk2(w, w);
        fma2(acc0, sA[k * 9 + 2 * g], wp);
        fma2(acc1, sA[k * 9 + 2 * g + 1], wp);
    }
    float bhc = bh[c];
    float x0, x1;
    upk2(acc0, x0, x1);
    g_outF[(size_t)(r0 + 4 * g + 0) * D + c] = fmaxf(x0 + bhc, 0.f);
    g_outF[(size_t)(r0 + 4 * g + 1) * D + c] = fmaxf(x1 + bhc, 0.f);
    upk2(acc1, x0, x1);
    g_outF[(size_t)(r0 + 4 * g + 2) * D + c] = fmaxf(x0 + bhc, 0.f);
    g_outF[(size_t)(r0 + 4 * g + 3) * D + c] = fmaxf(x1 + bhc, 0.f);
}

// ---------------- fully fused Set2Set (3 iters) + final MLP ---------------------
__global__ void k_s2s(const float* __restrict__ W_ih, const float* __restrict__ W_hh,
                      const float* __restrict__ b_ih, const float* __restrict__ b_hh,
                      const float* __restrict__ W1, const float* __restrict__ b1,
                      const float* __restrict__ W2, const float* __restrict__ b2,
                      float* __restrict__ out) {
    __shared__ __align__(16) float sqs[2 * D];
    __shared__ __align__(16) float shh[D], scc[D], sq[D], sg[4 * D];
    __shared__ float red[256];
    int b = blockIdx.x, tid = threadIdx.x;  // 256
    if (tid < 2 * D) sqs[tid] = 0.f;
    if (tid < D) { shh[tid] = 0.f; scc[tid] = 0.f; }
    int start = g_gstart[b], cnt = g_gcnt[b];
    __syncthreads();
    for (int it = 0; it < 3; it++) {
        // LSTM gates, j = tid
        float acc = b_ih[tid] + b_hh[tid];
        const float4* wi = (const float4*)(W_ih + tid * 2 * D);
#pragma unroll
        for (int k = 0; k < 2 * D / 4; k++) {
            float4 w = wi[k];
            acc += w.x * sqs[4 * k] + w.y * sqs[4 * k + 1] + w.z * sqs[4 * k + 2] + w.w * sqs[4 * k + 3];
        }
        const float4* wh = (const float4*)(W_hh + tid * D);
#pragma unroll
        for (int k = 0; k < D / 4; k++) {
            float4 w = wh[k];
            acc += w.x * shh[4 * k] + w.y * shh[4 * k + 1] + w.z * shh[4 * k + 2] + w.w * shh[4 * k + 3];
        }
        sg[tid] = acc;
        __syncthreads();
        if (tid < D) {
            float ig = sg[tid], fg = sg[D + tid], gg = sg[2 * D + tid], og = sg[3 * D + tid];
            float c = sigf(fg) * scc[tid] + sigf(ig) * tanhf(gg);
            float hv = sigf(og) * tanhf(c);
            scc[tid] = c; shh[tid] = hv; sq[tid] = hv;
        }
        __syncthreads();
        // attention pass 1: scores + max
        float lm = -3.0e38f;
        const float4* q4 = (const float4*)sq;
        for (int i = tid; i < cnt; i += 256) {
            int n = start + i;
            const float4* orow = (const float4*)(g_outF + (size_t)n * D);
            float e = 0.f;
#pragma unroll
            for (int j = 0; j < 16; j++) {
                float4 o = orow[j], qv = q4[j];
                e += o.x * qv.x + o.y * qv.y + o.z * qv.z + o.w * qv.w;
            }
            g_w2[n] = e;
            lm = fmaxf(lm, e);
        }
        red[tid] = lm;
        __syncthreads();
        for (int o = 128; o > 0; o >>= 1) {
            if (tid < o) red[tid] = fmaxf(red[tid], red[tid + o]);
            __syncthreads();
        }
        float m2 = red[0];
        __syncthreads();
        // pass 2: exp + sum
        float ls = 0.f;
        for (int i = tid; i < cnt; i += 256) {
            int n = start + i;
            float w = __expf(g_w2[n] - m2);
            g_w2[n] = w;
            ls += w;
        }
        red[tid] = ls;
        __syncthreads();
        for (int o = 128; o > 0; o >>= 1) {
            if (tid < o) red[tid] += red[tid + o];
            __syncthreads();
        }
        float s2 = red[0];
        __syncthreads();
        // pass 3: weighted readout
        int c = tid & 63, g = tid >> 6;
        float racc = 0.f;
        for (int i = g; i < cnt; i += 4) {
            int n = start + i;
            racc += g_w2[n] * g_outF[(size_t)n * D + c];
        }
        red[tid] = racc;
        __syncthreads();
        if (tid < 64) {
            float r = red[tid] + red[64 + tid] + red[128 + tid] + red[192 + tid];
            sqs[D + tid] = (cnt > 0) ? r / s2 : 0.f;
            sqs[tid] = sq[tid];
        }
        __syncthreads();
    }
    // final MLP: y = relu(q_star @ W1 + b1) . W2 + b2
    if (tid < D) {
        float acc = b1[tid];
        for (int k = 0; k < 2 * D; k++) acc = fmaf(sqs[k], W1[k * D + tid], acc);
        red[tid] = fmaxf(acc, 0.f) * W2[tid];
    }
    __syncthreads();
    if (tid < 32) red[tid] += red[tid + 32];
    __syncthreads();
    if (tid < 16) red[tid] += red[tid + 16];
    __syncthreads();
    if (tid < 8) red[tid] += red[tid + 8];
    __syncthreads();
    if (tid < 4) red[tid] += red[tid + 4];
    __syncthreads();
    if (tid < 2) red[tid] += red[tid + 2];
    __syncthreads();
    if (tid == 0) out[b] = red[0] + red[1] + b2[0];
}

// ---------------- launch --------------------------------------------------------
extern "C" void kernel_launch(void* const* d_in, const int* in_sizes, int n_in,
                              void* d_out, int out_size) {
    const float* x        = (const float*)d_in[0];
    const void*  ei       = d_in[1];
    const void*  bat      = d_in[2];
    const float* W0       = (const float*)d_in[3];
    const float* b0       = (const float*)d_in[4];
    const float* Wg       = (const float*)d_in[5];
    const float* att_src  = (const float*)d_in[6];
    const float* att_dst  = (const float*)d_in[7];
    const float* bg       = (const float*)d_in[8];
    const float* Wh       = (const float*)d_in[9];
    const float* bh       = (const float*)d_in[10];
    const float* W_ih     = (const float*)d_in[11];
    const float* W_hh     = (const float*)d_in[12];
    const float* b_ih     = (const float*)d_in[13];
    const float* b_hh     = (const float*)d_in[14];
    const float* W1       = (const float*)d_in[15];
    const float* b1       = (const float*)d_in[16];
    const float* W2       = (const float*)d_in[17];
    const float* b2       = (const float*)d_in[18];
    float* out            = (float*)d_out;

    k_detect<<<1, 32>>>(ei);
    k_cvt<<<(2 * Ee + 255) / 256, 256>>>(ei, bat);
    k_init<<<(Nn + 255) / 256, 256>>>();
    k_xh<<<Nn / 32, 256>>>(x, W0, b0, Wg);
    k_att<<<(Nn * HD + 255) / 256, 256>>>(att_src, att_dst);
    k_hist<<<(ET + 255) / 256, 256>>>();
    k_scan<<<1, 1024>>>();
    k_scatter<<<(ET + 255) / 256, 256>>>();
    k_agg<<<Nn / 8, 256>>>();
    k_out<<<Nn / 16, 256>>>(bg, Wh, bh);
    k_s2s<<<Bb, 256>>>(W_ih, W_hh, b_ih, b_hh, W1, b1, W2, b2, out);
}

// round 6
// speedup vs baseline: 1.3453x; 1.3453x over previous
#include <cuda_runtime.h>
#include <math.h>

#define Nn 20000
#define Ee 320000
#define ET (Ee + Nn)
#define Bb 128
#define IN_F 25
#define D 64
#define HD 8
#define HDD (HD * D) /* 512 */

// ---------------- scratch (static device globals; no allocation) ----------------
__device__ float g_xh[Nn * HDD];        // 41 MB
__device__ float g_as[Nn * HD];
__device__ float g_ad[Nn * HD];
__device__ int   g_cnt[Nn];
__device__ int   g_off[Nn + 1];
__device__ int   g_cur[Nn];
__device__ int   g_esrc[ET];
__device__ float g_agg[Nn * HDD];       // 41 MB
__device__ float g_outF[Nn * D];        // 5.1 MB
__device__ int   g_gstart[Bb];
__device__ int   g_gcnt[Bb];
__device__ float g_w2[Nn];
__device__ int   g_is64;
__device__ int   g_eidx[2 * Ee];

__device__ __forceinline__ float sigf(float x) { return 1.0f / (1.0f + __expf(-x)); }

// ---- packed fp32x2 helpers (Blackwell double-rate fp32) ----
__device__ __forceinline__ unsigned long long pk2(float lo, float hi) {
    unsigned long long r;
    asm("mov.b64 %0, {%1,%2};" : "=l"(r) : "f"(lo), "f"(hi));
    return r;
}
__device__ __forceinline__ void upk2(unsigned long long v, float& lo, float& hi) {
    asm("mov.b64 {%0,%1}, %2;" : "=f"(lo), "=f"(hi) : "l"(v));
}
__device__ __forceinline__ void fma2(unsigned long long& acc, unsigned long long a,
                                     unsigned long long b) {
    asm("fma.rn.f32x2 %0, %1, %2, %0;" : "+l"(acc) : "l"(a), "l"(b));
}

// ---------------- dtype probe ---------------------------------------------------
__global__ void k_detect(const void* __restrict__ ei) {
    if (threadIdx.x == 0) {
        const int2* p = (const int2*)ei;
        int ok64 = 1;
        for (int j = 0; j < 64; j++) if (p[j].y != 0) ok64 = 0;
        g_is64 = ok64;
    }
}

__global__ void k_init() {
    int i = blockIdx.x * blockDim.x + threadIdx.x;
    if (i < Nn) g_cnt[i] = 0;
    if (i < Bb) { g_gstart[i] = Nn; g_gcnt[i] = 0; }
}

// ---------------- convert indices + dst histogram + graph segments ---------------
__global__ void k_cvt_hist(const void* __restrict__ ei, const void* __restrict__ bat) {
    int i = blockIdx.x * blockDim.x + threadIdx.x;
    int is64 = g_is64;
    if (i < 2 * Ee) {
        int v = is64 ? (int)((const long long*)ei)[i] : ((const int*)ei)[i];
        g_eidx[i] = v;
        if (i >= Ee) atomicAdd(&g_cnt[v], 1);          // dst histogram
    }
    if (i < Nn) {
        int b = is64 ? (int)((const long long*)bat)[i] : ((const int*)bat)[i];
        atomicMin(&g_gstart[b], i);
        atomicAdd(&g_gcnt[b], 1);
        atomicAdd(&g_cnt[i], 1);                        // self-loop
    }
}

// ---------------- fused: h0 = relu(x@W0+b0); xh = h0@Wg  (16 rows/block) --------
// phase B uses packed f32x2 over COLUMN pairs: weight pair = 1 LDG.64,
// activation duplicated float2 in shared (no per-use pack), 16 u64 accs.
__global__ void k_xh(const float* __restrict__ x, const float* __restrict__ W0,
                     const float* __restrict__ b0, const float* __restrict__ Wg) {
    __shared__ float sx[16 * IN_F];
    __shared__ float sW[IN_F * D];
    __shared__ __align__(8) float2 sh2[64 * 17 + 1];   // [k][row] duplicated, pad 17
    int tid = threadIdx.x;  // 256
    int r0 = blockIdx.x * 16;
    for (int i = tid; i < 16 * IN_F; i += 256) sx[i] = x[r0 * IN_F + i];
    for (int i = tid; i < IN_F * D; i += 256) sW[i] = W0[i];
    __syncthreads();
    // phase A: h0 tile 16x64 -> sh2[k][r] = (a, a)
    for (int i = tid; i < 1024; i += 256) {
        int r = i >> 6, cc = i & 63;
        float a = b0[cc];
#pragma unroll
        for (int k = 0; k < IN_F; k++) a = fmaf(sx[r * IN_F + k], sW[k * D + cc], a);
        a = fmaxf(a, 0.f);
        sh2[cc * 17 + r] = make_float2(a, a);
    }
    __syncthreads();
    // phase B: cols (2*tid, 2*tid+1)
    const unsigned long long* S = (const unsigned long long*)sh2;
    unsigned long long acc[16];
#pragma unroll
    for (int r = 0; r < 16; r++) acc[r] = 0ULL;
#pragma unroll 2
    for (int k = 0; k < 64; k++) {
        unsigned long long wp = ((const unsigned long long*)(Wg + (size_t)k * HDD))[tid];
        const unsigned long long* row = S + k * 17;
#pragma unroll
        for (int r = 0; r < 16; r++) fma2(acc[r], row[r], wp);
    }
#pragma unroll
    for (int r = 0; r < 16; r++) {
        float lo, hi;
        upk2(acc[r], lo, hi);
        *(float2*)(g_xh + (size_t)(r0 + r) * HDD + 2 * tid) = make_float2(lo, hi);
    }
}

// ---------------- a_s, a_d ------------------------------------------------------
__global__ void k_att(const float* __restrict__ att_src, const float* __restrict__ att_dst) {
    int i = blockIdx.x * blockDim.x + threadIdx.x;  // i = n*8 + h
    if (i >= Nn * HD) return;
    int h = i & 7;
    const float4* xr = (const float4*)(g_xh + (size_t)i * D);
    const float4* a4 = (const float4*)(att_src + h * D);
    const float4* b4 = (const float4*)(att_dst + h * D);
    float s = 0.f, d = 0.f;
#pragma unroll
    for (int j = 0; j < 16; j++) {
        float4 v = xr[j], a = a4[j], b = b4[j];
        s += v.x * a.x + v.y * a.y + v.z * a.z + v.w * a.w;
        d += v.x * b.x + v.y * b.y + v.z * b.z + v.w * b.w;
    }
    g_as[i] = s;
    g_ad[i] = d;
}

// ---------------- single-block register-chunk scan (2 barriers) -----------------
__global__ void k_scan() {
    __shared__ int warpsum[32];
    int tid = threadIdx.x;  // 1024
    const int CH = 20;
    int base = tid * CH;
    int v[CH];
    int tot = 0;
#pragma unroll
    for (int i = 0; i < CH; i++) {
        int idx = base + i;
        int t = (idx < Nn) ? g_cnt[idx] : 0;
        v[i] = tot;
        tot += t;
    }
    int lane = tid & 31, wid = tid >> 5;
    int sc = tot;
#pragma unroll
    for (int o = 1; o < 32; o <<= 1) {
        int t = __shfl_up_sync(0xffffffff, sc, o);
        if (lane >= o) sc += t;
    }
    if (lane == 31) warpsum[wid] = sc;
    __syncthreads();
    if (wid == 0) {
        int s = warpsum[lane];
#pragma unroll
        for (int o = 1; o < 32; o <<= 1) {
            int t = __shfl_up_sync(0xffffffff, s, o);
            if (lane >= o) s += t;
        }
        warpsum[lane] = s;
    }
    __syncthreads();
    int basesum = sc - tot + (wid ? warpsum[wid - 1] : 0);
#pragma unroll
    for (int i = 0; i < CH; i++) {
        int idx = base + i;
        if (idx < Nn) {
            int e = basesum + v[i];
            g_off[idx] = e;
            g_cur[idx] = e;
        }
    }
    if (tid == 1023) g_off[Nn] = basesum + tot;
}

__global__ void k_scatter() {
    int e = blockIdx.x * blockDim.x + threadIdx.x;
    if (e >= ET) return;
    int src, dst;
    if (e < Ee) { src = g_eidx[e]; dst = g_eidx[Ee + e]; }
    else        { src = e - Ee;    dst = src; }
    int p = atomicAdd(&g_cur[dst], 1);
    g_esrc[p] = src;
}

// ---------------- fused per-dst segment softmax + aggregation -------------------
#define FMA4(A, R) { A.x += w * R.x; A.y += w * R.y; A.z += w * R.z; A.w += w * R.w; }
__global__ void k_agg() {
    int warp = (blockIdx.x * blockDim.x + threadIdx.x) >> 5;
    int lane = threadIdx.x & 31;
    if (warp >= Nn) return;
    int v = warp;
    int beg = g_off[v], end = g_off[v + 1];
    int h = lane >> 2;
    float adh = g_ad[v * HD + h];

    float mx = -1e30f;
    for (int i = beg; i < end; i++) {
        int s = g_esrc[i];
        float e = g_as[s * HD + h] + adh;
        e = (e > 0.f) ? e : 0.2f * e;
        mx = fmaxf(mx, e);
    }
    float ssum = 0.f;
    float4 a0 = {0, 0, 0, 0}, a1 = {0, 0, 0, 0}, a2 = {0, 0, 0, 0}, a3 = {0, 0, 0, 0};
    for (int i = beg; i < end; i++) {
        int s = g_esrc[i];
        float e = g_as[s * HD + h] + adh;
        e = (e > 0.f) ? e : 0.2f * e;
        float w = __expf(e - mx);
        ssum += w;
        const float4* row = (const float4*)(g_xh + (size_t)s * HDD) + lane * 4;
        float4 r0 = row[0], r1 = row[1], r2 = row[2], r3 = row[3];
        FMA4(a0, r0); FMA4(a1, r1); FMA4(a2, r2); FMA4(a3, r3);
    }
    float inv = 1.f / ssum;
    float4* o = (float4*)(g_agg + (size_t)v * HDD) + lane * 4;
    o[0] = make_float4(a0.x * inv, a0.y * inv, a0.z * inv, a0.w * inv);
    o[1] = make_float4(a1.x * inv, a1.y * inv, a1.z * inv, a1.w * inv);
    o[2] = make_float4(a2.x * inv, a2.y * inv, a2.z * inv, a2.w * inv);
    o[3] = make_float4(a3.x * inv, a3.y * inv, a3.z * inv, a3.w * inv);
}

// ---------------- out = relu(relu(agg + bg) @ Wh + bh)  (R4 scalar version) -----
__global__ void k_out(const float* __restrict__ bg, const float* __restrict__ Wh,
                      const float* __restrict__ bh) {
    __shared__ __align__(16) float sA[16 * HDD];  // 32 KB
    int tid = threadIdx.x;
    int r0 = blockIdx.x * 16;
    const float4* src = (const float4*)(g_agg + (size_t)r0 * HDD);
    const float4* bg4 = (const float4*)bg;
    float4* dstS = (float4*)sA;
    for (int i = tid; i < 16 * HDD / 4; i += 256) {
        float4 a = src[i];
        float4 b = bg4[i & 127];
        a.x = fmaxf(a.x + b.x, 0.f); a.y = fmaxf(a.y + b.y, 0.f);
        a.z = fmaxf(a.z + b.z, 0.f); a.w = fmaxf(a.w + b.w, 0.f);
        dstS[i] = a;
    }
    __syncthreads();
    int c = tid & 63, rg = tid >> 6;
    float acc[4] = {0.f, 0.f, 0.f, 0.f};
    for (int k = 0; k < HDD; k += 4) {
        float w0 = Wh[(k + 0) * D + c];
        float w1 = Wh[(k + 1) * D + c];
        float w2 = Wh[(k + 2) * D + c];
        float w3 = Wh[(k + 3) * D + c];
#pragma unroll
        for (int r = 0; r < 4; r++) {
            float4 a = *(const float4*)&sA[(rg * 4 + r) * HDD + k];
            acc[r] += a.x * w0 + a.y * w1 + a.z * w2 + a.w * w3;
        }
    }
    float bhc = bh[c];
#pragma unroll
    for (int r = 0; r < 4; r++)
        g_outF[(size_t)(r0 + rg * 4 + r) * D + c] = fmaxf(acc[r] + bhc, 0.f);
}

// ---------------- fully fused Set2Set (3 iters) + final MLP ---------------------
__global__ void k_s2s(const float* __restrict__ W_ih, const float* __restrict__ W_hh,
                      const float* __restrict__ b_ih, const float* __restrict__ b_hh,
                      const float* __restrict__ W1, const float* __restrict__ b1,
                      const float* __restrict__ W2, const float* __restrict__ b2,
                      float* __restrict__ out) {
    __shared__ __align__(16) float sqs[2 * D];
    __shared__ __align__(16) float shh[D], scc[D], sq[D], sg[4 * D];
    __shared__ float red[256];
    int b = blockIdx.x, tid = threadIdx.x;  // 256
    if (tid < 2 * D) sqs[tid] = 0.f;
    if (tid < D) { shh[tid] = 0.f; scc[tid] = 0.f; }
    int start = g_gstart[b], cnt = g_gcnt[b];
    __syncthreads();
    for (int it = 0; it < 3; it++) {
        float acc = b_ih[tid] + b_hh[tid];
        const float4* wi = (const float4*)(W_ih + tid * 2 * D);
#pragma unroll
        for (int k = 0; k < 2 * D / 4; k++) {
            float4 w = wi[k];
            acc += w.x * sqs[4 * k] + w.y * sqs[4 * k + 1] + w.z * sqs[4 * k + 2] + w.w * sqs[4 * k + 3];
        }
        const float4* wh = (const float4*)(W_hh + tid * D);
#pragma unroll
        for (int k = 0; k < D / 4; k++) {
            float4 w = wh[k];
            acc += w.x * shh[4 * k] + w.y * shh[4 * k + 1] + w.z * shh[4 * k + 2] + w.w * shh[4 * k + 3];
        }
        sg[tid] = acc;
        __syncthreads();
        if (tid < D) {
            float ig = sg[tid], fg = sg[D + tid], gg = sg[2 * D + tid], og = sg[3 * D + tid];
            float c = sigf(fg) * scc[tid] + sigf(ig) * tanhf(gg);
            float hv = sigf(og) * tanhf(c);
            scc[tid] = c; shh[tid] = hv; sq[tid] = hv;
        }
        __syncthreads();
        float lm = -3.0e38f;
        const float4* q4 = (const float4*)sq;
        for (int i = tid; i < cnt; i += 256) {
            int n = start + i;
            const float4* orow = (const float4*)(g_outF + (size_t)n * D);
            float e = 0.f;
#pragma unroll
            for (int j = 0; j < 16; j++) {
                float4 o = orow[j], qv = q4[j];
                e += o.x * qv.x + o.y * qv.y + o.z * qv.z + o.w * qv.w;
            }
            g_w2[n] = e;
            lm = fmaxf(lm, e);
        }
        red[tid] = lm;
        __syncthreads();
        for (int o = 128; o > 0; o >>= 1) {
            if (tid < o) red[tid] = fmaxf(red[tid], red[tid + o]);
            __syncthreads();
        }
        float m2 = red[0];
        __syncthreads();
        float ls = 0.f;
        for (int i = tid; i < cnt; i += 256) {
            int n = start + i;
            float w = __expf(g_w2[n] - m2);
            g_w2[n] = w;
            ls += w;
        }
        red[tid] = ls;
        __syncthreads();
        for (int o = 128; o > 0; o >>= 1) {
            if (tid < o) red[tid] += red[tid + o];
            __syncthreads();
        }
        float s2 = red[0];
        __syncthreads();
        int c = tid & 63, g = tid >> 6;
        float racc = 0.f;
        for (int i = g; i < cnt; i += 4) {
            int n = start + i;
            racc += g_w2[n] * g_outF[(size_t)n * D + c];
        }
        red[tid] = racc;
        __syncthreads();
        if (tid < 64) {
            float r = red[tid] + red[64 + tid] + red[128 + tid] + red[192 + tid];
            sqs[D + tid] = (cnt > 0) ? r / s2 : 0.f;
            sqs[tid] = sq[tid];
        }
        __syncthreads();
    }
    if (tid < D) {
        float acc = b1[tid];
        for (int k = 0; k < 2 * D; k++) acc = fmaf(sqs[k], W1[k * D + tid], acc);
        red[tid] = fmaxf(acc, 0.f) * W2[tid];
    }
    __syncthreads();
    if (tid < 32) red[tid] += red[tid + 32];
    __syncthreads();
    if (tid < 16) red[tid] += red[tid + 16];
    __syncthreads();
    if (tid < 8) red[tid] += red[tid + 8];
    __syncthreads();
    if (tid < 4) red[tid] += red[tid + 4];
    __syncthreads();
    if (tid < 2) red[tid] += red[tid + 2];
    __syncthreads();
    if (tid == 0) out[b] = red[0] + red[1] + b2[0];
}

// ---------------- launch --------------------------------------------------------
extern "C" void kernel_launch(void* const* d_in, const int* in_sizes, int n_in,
                              void* d_out, int out_size) {
    const float* x        = (const float*)d_in[0];
    const void*  ei       = d_in[1];
    const void*  bat      = d_in[2];
    const float* W0       = (const float*)d_in[3];
    const float* b0       = (const float*)d_in[4];
    const float* Wg       = (const float*)d_in[5];
    const float* att_src  = (const float*)d_in[6];
    const float* att_dst  = (const float*)d_in[7];
    const float* bg       = (const float*)d_in[8];
    const float* Wh       = (const float*)d_in[9];
    const float* bh       = (const float*)d_in[10];
    const float* W_ih     = (const float*)d_in[11];
    const float* W_hh     = (const float*)d_in[12];
    const float* b_ih     = (const float*)d_in[13];
    const float* b_hh     = (const float*)d_in[14];
    const float* W1       = (const float*)d_in[15];
    const float* b1       = (const float*)d_in[16];
    const float* W2       = (const float*)d_in[17];
    const float* b2       = (const float*)d_in[18];
    float* out            = (float*)d_out;

    k_detect<<<1, 32>>>(ei);
    k_init<<<(Nn + 255) / 256, 256>>>();
    k_cvt_hist<<<(2 * Ee + 255) / 256, 256>>>(ei, bat);
    k_xh<<<Nn / 16, 256>>>(x, W0, b0, Wg);
    k_att<<<(Nn * HD + 255) / 256, 256>>>(att_src, att_dst);
    k_scan<<<1, 1024>>>();
    k_scatter<<<(ET + 255) / 256, 256>>>();
    k_agg<<<Nn / 8, 256>>>();
    k_out<<<Nn / 16, 256>>>(bg, Wh, bh);
    k_s2s<<<Bb, 256>>>(W_ih, W_hh, b_ih, b_hh, W1, b1, W2, b2, out);
}

// round 7
// speedup vs baseline: 1.6464x; 1.2238x over previous
#include <cuda_runtime.h>
#include <math.h>

#define Nn 20000
#define Ee 320000
#define ET (Ee + Nn)
#define Bb 128
#define IN_F 25
#define D 64
#define HD 8
#define HDD (HD * D) /* 512 */

// ---------------- scratch (static device globals; no allocation) ----------------
__device__ float g_h0[Nn * D];          // 5.1 MB (L2-resident)
__device__ float g_as[Nn * HD];
__device__ float g_ad[Nn * HD];
__device__ float g_cs[HD * D];          // Wg_h @ att_src[h]
__device__ float g_cd[HD * D];
__device__ int   g_cnt[Nn];
__device__ int   g_off[Nn + 1];
__device__ int   g_cur[Nn];
__device__ int   g_esrc[ET];
__device__ float g_p[Nn * HDD];         // aggregated h0 per head, 41 MB
__device__ float g_outF[Nn * D];        // 5.1 MB
__device__ int   g_gstart[Bb];
__device__ int   g_gcnt[Bb];
__device__ float g_w2[Nn];
__device__ int   g_is64;
__device__ int   g_eidx[2 * Ee];

__device__ __forceinline__ float sigf(float x) { return 1.0f / (1.0f + __expf(-x)); }

// ---------------- dtype probe ---------------------------------------------------
__global__ void k_detect(const void* __restrict__ ei) {
    if (threadIdx.x == 0) {
        const int2* p = (const int2*)ei;
        int ok64 = 1;
        for (int j = 0; j < 64; j++) if (p[j].y != 0) ok64 = 0;
        g_is64 = ok64;
    }
}

__global__ void k_init() {
    int i = blockIdx.x * blockDim.x + threadIdx.x;
    if (i < Nn) g_cnt[i] = 0;
    if (i < Bb) { g_gstart[i] = Nn; g_gcnt[i] = 0; }
}

// ---------------- convert indices + dst histogram + graph segments --------------
__global__ void k_cvt_hist(const void* __restrict__ ei, const void* __restrict__ bat) {
    int i = blockIdx.x * blockDim.x + threadIdx.x;
    int is64 = g_is64;
    if (i < 2 * Ee) {
        int v = is64 ? (int)((const long long*)ei)[i] : ((const int*)ei)[i];
        g_eidx[i] = v;
        if (i >= Ee) atomicAdd(&g_cnt[v], 1);          // dst histogram
    }
    if (i < Nn) {
        int b = is64 ? (int)((const long long*)bat)[i] : ((const int*)bat)[i];
        atomicMin(&g_gstart[b], i);
        atomicAdd(&g_gcnt[b], 1);
        atomicAdd(&g_cnt[i], 1);                        // self-loop
    }
}

// ---------------- c_s[h,k] = sum_c Wg[k, h*64+c] * att_src[h,c] ------------------
__global__ void k_catt(const float* __restrict__ Wg, const float* __restrict__ att_src,
                       const float* __restrict__ att_dst) {
    int h = threadIdx.x >> 6, k = threadIdx.x & 63;   // 512 threads
    float s = 0.f, d = 0.f;
    const float* wr = Wg + (size_t)k * HDD + h * D;
    const float* as = att_src + h * D;
    const float* ad = att_dst + h * D;
#pragma unroll 8
    for (int c = 0; c < D; c++) {
        float w = wr[c];
        s = fmaf(w, as[c], s);
        d = fmaf(w, ad[c], d);
    }
    g_cs[h * D + k] = s;
    g_cd[h * D + k] = d;
}

// ---------------- h0 = relu(x@W0+b0);  a_s/a_d = h0 . c_s/c_d -------------------
__global__ void k_h0att(const float* __restrict__ x, const float* __restrict__ W0,
                        const float* __restrict__ b0) {
    __shared__ float sx[16 * IN_F];
    __shared__ float sW[IN_F * D];
    __shared__ float sh[16][65];   // padded
    int tid = threadIdx.x;  // 256
    int r0 = blockIdx.x * 16;
    for (int i = tid; i < 16 * IN_F; i += 256) sx[i] = x[r0 * IN_F + i];
    for (int i = tid; i < IN_F * D; i += 256) sW[i] = W0[i];
    __syncthreads();
    for (int i = tid; i < 1024; i += 256) {
        int r = i >> 6, c = i & 63;
        float a = b0[c];
#pragma unroll
        for (int k = 0; k < IN_F; k++) a = fmaf(sx[r * IN_F + k], sW[k * D + c], a);
        sh[r][c] = fmaxf(a, 0.f);
    }
    __syncthreads();
    // write h0 (float4)
    {
        int r = tid >> 4, q = tid & 15;
        float4 v = make_float4(sh[r][q * 4], sh[r][q * 4 + 1], sh[r][q * 4 + 2], sh[r][q * 4 + 3]);
        *(float4*)(g_h0 + (size_t)(r0 + r) * D + q * 4) = v;
    }
    // attention logits: thread = (row, head, side)
    {
        int r = tid >> 4, hs = tid & 15, h = hs >> 1;
        const float* cv = (hs & 1) ? g_cd : g_cs;
        float a = 0.f;
#pragma unroll 8
        for (int k = 0; k < D; k++) a = fmaf(sh[r][k], cv[h * D + k], a);
        if (hs & 1) g_ad[(r0 + r) * HD + h] = a;
        else        g_as[(r0 + r) * HD + h] = a;
    }
}

// ---------------- single-block register-chunk scan (2 barriers) -----------------
__global__ void k_scan() {
    __shared__ int warpsum[32];
    int tid = threadIdx.x;  // 1024
    const int CH = 20;
    int base = tid * CH;
    int v[CH];
    int tot = 0;
#pragma unroll
    for (int i = 0; i < CH; i++) {
        int idx = base + i;
        int t = (idx < Nn) ? g_cnt[idx] : 0;
        v[i] = tot;
        tot += t;
    }
    int lane = tid & 31, wid = tid >> 5;
    int sc = tot;
#pragma unroll
    for (int o = 1; o < 32; o <<= 1) {
        int t = __shfl_up_sync(0xffffffff, sc, o);
        if (lane >= o) sc += t;
    }
    if (lane == 31) warpsum[wid] = sc;
    __syncthreads();
    if (wid == 0) {
        int s = warpsum[lane];
#pragma unroll
        for (int o = 1; o < 32; o <<= 1) {
            int t = __shfl_up_sync(0xffffffff, s, o);
            if (lane >= o) s += t;
        }
        warpsum[lane] = s;
    }
    __syncthreads();
    int basesum = sc - tot + (wid ? warpsum[wid - 1] : 0);
#pragma unroll
    for (int i = 0; i < CH; i++) {
        int idx = base + i;
        if (idx < Nn) {
            int e = basesum + v[i];
            g_off[idx] = e;
            g_cur[idx] = e;
        }
    }
    if (tid == 1023) g_off[Nn] = basesum + tot;
}

__global__ void k_scatter() {
    int e = blockIdx.x * blockDim.x + threadIdx.x;
    if (e >= ET) return;
    int src, dst;
    if (e < Ee) { src = g_eidx[e]; dst = g_eidx[Ee + e]; }
    else        { src = e - Ee;    dst = src; }
    int p = atomicAdd(&g_cur[dst], 1);
    g_esrc[p] = src;
}

// ---------------- fused segment softmax + h0 aggregation (64-dim gather!) -------
// warp per dst. lanes 0-7 own head logits; every lane owns dim-pair (2*lane).
__global__ void k_agg() {
    int warp = (blockIdx.x * blockDim.x + threadIdx.x) >> 5;
    int lane = threadIdx.x & 31;
    if (warp >= Nn) return;
    int v = warp;
    int beg = g_off[v], end = g_off[v + 1];
    float adh = (lane < 8) ? g_ad[v * HD + lane] : 0.f;

    float mx = -1e30f;
    for (int i = beg; i < end; i++) {
        int s = g_esrc[i];
        if (lane < 8) {
            float e = g_as[s * HD + lane] + adh;
            e = (e > 0.f) ? e : 0.2f * e;
            mx = fmaxf(mx, e);
        }
    }
    float ssum = 0.f;
    float2 acc[8];
#pragma unroll
    for (int h = 0; h < 8; h++) acc[h] = make_float2(0.f, 0.f);
    for (int i = beg; i < end; i++) {
        int s = g_esrc[i];
        float w = 0.f;
        if (lane < 8) {
            float e = g_as[s * HD + lane] + adh;
            e = (e > 0.f) ? e : 0.2f * e;
            w = __expf(e - mx);
            ssum += w;
        }
        float2 hp = *((const float2*)(g_h0 + (size_t)s * D) + lane);
#pragma unroll
        for (int h = 0; h < 8; h++) {
            float wh = __shfl_sync(0xffffffff, w, h);
            acc[h].x = fmaf(wh, hp.x, acc[h].x);
            acc[h].y = fmaf(wh, hp.y, acc[h].y);
        }
    }
    float invl = (lane < 8) ? 1.f / ssum : 0.f;
#pragma unroll
    for (int h = 0; h < 8; h++) {
        float iv = __shfl_sync(0xffffffff, invl, h);
        *((float2*)(g_p + (size_t)v * HDD + h * D) + lane) =
            make_float2(acc[h].x * iv, acc[h].y * iv);
    }
}

// ---------------- fused: t = relu(p @ blockdiag(Wg_h) + bg); out = relu(t@Wh+bh) -
__global__ void k_big(const float* __restrict__ Wg, const float* __restrict__ bg,
                      const float* __restrict__ Wh, const float* __restrict__ bh) {
    __shared__ __align__(16) float sp[16 * HDD];  // 32 KB
    int tid = threadIdx.x;  // 256
    int r0 = blockIdx.x * 16;
    {
        const float4* src = (const float4*)(g_p + (size_t)r0 * HDD);
        float4* dst = (float4*)sp;
        for (int i = tid; i < 2048; i += 256) dst[i] = src[i];
    }
    __syncthreads();
    int c = tid & 63, rg = tid >> 6;  // rows rg*4 .. rg*4+3
    // phase 1: per-head 64x64 GEMM, in-place overwrite per head block
    for (int h = 0; h < HD; h++) {
        float acc[4] = {0.f, 0.f, 0.f, 0.f};
        int base = h * D;
        for (int k = 0; k < D; k += 4) {
            float w0 = Wg[(size_t)(k + 0) * HDD + base + c];
            float w1 = Wg[(size_t)(k + 1) * HDD + base + c];
            float w2 = Wg[(size_t)(k + 2) * HDD + base + c];
            float w3 = Wg[(size_t)(k + 3) * HDD + base + c];
#pragma unroll
            for (int r = 0; r < 4; r++) {
                float4 a = *(const float4*)&sp[(rg * 4 + r) * HDD + base + k];
                acc[r] += a.x * w0 + a.y * w1 + a.z * w2 + a.w * w3;
            }
        }
        float bgc = bg[base + c];
        __syncthreads();  // all reads of head block h done
#pragma unroll
        for (int r = 0; r < 4; r++)
            sp[(rg * 4 + r) * HDD + base + c] = fmaxf(acc[r] + bgc, 0.f);
    }
    __syncthreads();
    // phase 2: dense 512 -> 64
    float acc[4] = {0.f, 0.f, 0.f, 0.f};
    for (int j = 0; j < HDD; j += 4) {
        float w0 = Wh[(size_t)(j + 0) * D + c];
        float w1 = Wh[(size_t)(j + 1) * D + c];
        float w2 = Wh[(size_t)(j + 2) * D + c];
        float w3 = Wh[(size_t)(j + 3) * D + c];
#pragma unroll
        for (int r = 0; r < 4; r++) {
            float4 a = *(const float4*)&sp[(rg * 4 + r) * HDD + j];
            acc[r] += a.x * w0 + a.y * w1 + a.z * w2 + a.w * w3;
        }
    }
    float bhc = bh[c];
#pragma unroll
    for (int r = 0; r < 4; r++)
        g_outF[(size_t)(r0 + rg * 4 + r) * D + c] = fmaxf(acc[r] + bhc, 0.f);
}

// ---------------- fully fused Set2Set (3 iters) + final MLP ---------------------
__global__ void k_s2s(const float* __restrict__ W_ih, const float* __restrict__ W_hh,
                      const float* __restrict__ b_ih, const float* __restrict__ b_hh,
                      const float* __restrict__ W1, const float* __restrict__ b1,
                      const float* __restrict__ W2, const float* __restrict__ b2,
                      float* __restrict__ out) {
    __shared__ __align__(16) float sqs[2 * D];
    __shared__ __align__(16) float shh[D], scc[D], sq[D], sg[4 * D];
    __shared__ float red[256];
    int b = blockIdx.x, tid = threadIdx.x;  // 256
    if (tid < 2 * D) sqs[tid] = 0.f;
    if (tid < D) { shh[tid] = 0.f; scc[tid] = 0.f; }
    int start = g_gstart[b], cnt = g_gcnt[b];
    __syncthreads();
    for (int it = 0; it < 3; it++) {
        float acc = b_ih[tid] + b_hh[tid];
        const float4* wi = (const float4*)(W_ih + tid * 2 * D);
#pragma unroll
        for (int k = 0; k < 2 * D / 4; k++) {
            float4 w = wi[k];
            acc += w.x * sqs[4 * k] + w.y * sqs[4 * k + 1] + w.z * sqs[4 * k + 2] + w.w * sqs[4 * k + 3];
        }
        const float4* wh = (const float4*)(W_hh + tid * D);
#pragma unroll
        for (int k = 0; k < D / 4; k++) {
            float4 w = wh[k];
            acc += w.x * shh[4 * k] + w.y * shh[4 * k + 1] + w.z * shh[4 * k + 2] + w.w * shh[4 * k + 3];
        }
        sg[tid] = acc;
        __syncthreads();
        if (tid < D) {
            float ig = sg[tid], fg = sg[D + tid], gg = sg[2 * D + tid], og = sg[3 * D + tid];
            float c = sigf(fg) * scc[tid] + sigf(ig) * tanhf(gg);
            float hv = sigf(og) * tanhf(c);
            scc[tid] = c; shh[tid] = hv; sq[tid] = hv;
        }
        __syncthreads();
        float lm = -3.0e38f;
        const float4* q4 = (const float4*)sq;
        for (int i = tid; i < cnt; i += 256) {
            int n = start + i;
            const float4* orow = (const float4*)(g_outF + (size_t)n * D);
            float e = 0.f;
#pragma unroll
            for (int j = 0; j < 16; j++) {
                float4 o = orow[j], qv = q4[j];
                e += o.x * qv.x + o.y * qv.y + o.z * qv.z + o.w * qv.w;
            }
            g_w2[n] = e;
            lm = fmaxf(lm, e);
        }
        red[tid] = lm;
        __syncthreads();
        for (int o = 128; o > 0; o >>= 1) {
            if (tid < o) red[tid] = fmaxf(red[tid], red[tid + o]);
            __syncthreads();
        }
        float m2 = red[0];
        __syncthreads();
        float ls = 0.f;
        for (int i = tid; i < cnt; i += 256) {
            int n = start + i;
            float w = __expf(g_w2[n] - m2);
            g_w2[n] = w;
            ls += w;
        }
        red[tid] = ls;
        __syncthreads();
        for (int o = 128; o > 0; o >>= 1) {
            if (tid < o) red[tid] += red[tid + o];
            __syncthreads();
        }
        float s2 = red[0];
        __syncthreads();
        int c = tid & 63, g = tid >> 6;
        float racc = 0.f;
        for (int i = g; i < cnt; i += 4) {
            int n = start + i;
            racc += g_w2[n] * g_outF[(size_t)n * D + c];
        }
        red[tid] = racc;
        __syncthreads();
        if (tid < 64) {
            float r = red[tid] + red[64 + tid] + red[128 + tid] + red[192 + tid];
            sqs[D + tid] = (cnt > 0) ? r / s2 : 0.f;
            sqs[tid] = sq[tid];
        }
        __syncthreads();
    }
    if (tid < D) {
        float acc = b1[tid];
        for (int k = 0; k < 2 * D; k++) acc = fmaf(sqs[k], W1[k * D + tid], acc);
        red[tid] = fmaxf(acc, 0.f) * W2[tid];
    }
    __syncthreads();
    if (tid < 32) red[tid] += red[tid + 32];
    __syncthreads();
    if (tid < 16) red[tid] += red[tid + 16];
    __syncthreads();
    if (tid < 8) red[tid] += red[tid + 8];
    __syncthreads();
    if (tid < 4) red[tid] += red[tid + 4];
    __syncthreads();
    if (tid < 2) red[tid] += red[tid + 2];
    __syncthreads();
    if (tid == 0) out[b] = red[0] + red[1] + b2[0];
}

// ---------------- launch --------------------------------------------------------
extern "C" void kernel_launch(void* const* d_in, const int* in_sizes, int n_in,
                              void* d_out, int out_size) {
    const float* x        = (const float*)d_in[0];
    const void*  ei       = d_in[1];
    const void*  bat      = d_in[2];
    const float* W0       = (const float*)d_in[3];
    const float* b0       = (const float*)d_in[4];
    const float* Wg       = (const float*)d_in[5];
    const float* att_src  = (const float*)d_in[6];
    const float* att_dst  = (const float*)d_in[7];
    const float* bg       = (const float*)d_in[8];
    const float* Wh       = (const float*)d_in[9];
    const float* bh       = (const float*)d_in[10];
    const float* W_ih     = (const float*)d_in[11];
    const float* W_hh     = (const float*)d_in[12];
    const float* b_ih     = (const float*)d_in[13];
    const float* b_hh     = (const float*)d_in[14];
    const float* W1       = (const float*)d_in[15];
    const float* b1       = (const float*)d_in[16];
    const float* W2       = (const float*)d_in[17];
    const float* b2       = (const float*)d_in[18];
    float* out            = (float*)d_out;

    k_detect<<<1, 32>>>(ei);
    k_init<<<(Nn + 255) / 256, 256>>>();
    k_cvt_hist<<<(2 * Ee + 255) / 256, 256>>>(ei, bat);
    k_catt<<<1, 512>>>(Wg, att_src, att_dst);
    k_h0att<<<Nn / 16, 256>>>(x, W0, b0);
    k_scan<<<1, 1024>>>();
    k_scatter<<<(ET + 255) / 256, 256>>>();
    k_agg<<<(Nn * 32 + 255) / 256, 256>>>();
    k_big<<<Nn / 16, 256>>>(Wg, bg, Wh, bh);
    k_s2s<<<Bb, 256>>>(W_ih, W_hh, b_ih, b_hh, W1, b1, W2, b2, out);
}

// round 10
// speedup vs baseline: 1.8756x; 1.1392x over previous
#include <cuda_runtime.h>
#include <math.h>

#define Nn 20000
#define Ee 320000
#define ET (Ee + Nn)
#define Bb 128
#define IN_F 25
#define D 64
#define HD 8
#define HDD (HD * D) /* 512 */

// ---------------- scratch (static device globals; no allocation) ----------------
__device__ float g_h0[Nn * D];          // 5.1 MB (L2-resident)
__device__ float g_as[Nn * HD];
__device__ float g_ad[Nn * HD];
__device__ float g_cs[HD * D];          // Wg_h @ att_src[h]
__device__ float g_cd[HD * D];
__device__ int   g_cnt[Nn];
__device__ int   g_off[Nn + 1];
__device__ int   g_cur[Nn];
__device__ int   g_esrc[ET];
__device__ float g_p[Nn * HDD];         // aggregated h0 per head, 41 MB
__device__ float g_outF[Nn * D];        // 5.1 MB
__device__ int   g_gstart[Bb];
__device__ int   g_gcnt[Bb];
__device__ float g_w2[Nn];
__device__ int   g_is64;
__device__ int   g_eidx[2 * Ee];

__device__ __forceinline__ float sigf(float x) { return 1.0f / (1.0f + __expf(-x)); }

// ---- packed fp32x2 helpers ----
__device__ __forceinline__ unsigned long long pk2(float lo, float hi) {
    unsigned long long r;
    asm("mov.b64 %0, {%1,%2};" : "=l"(r) : "f"(lo), "f"(hi));
    return r;
}
__device__ __forceinline__ void upk2(unsigned long long v, float& lo, float& hi) {
    asm("mov.b64 {%0,%1}, %2;" : "=f"(lo), "=f"(hi) : "l"(v));
}
__device__ __forceinline__ void fma2(unsigned long long& acc, unsigned long long a,
                                     unsigned long long b) {
    asm("fma.rn.f32x2 %0, %1, %2, %0;" : "+l"(acc) : "l"(a), "l"(b));
}

// ---------------- fused prologue: detect dtype + init + c_s/c_d -----------------
// grid 128 x 256 = 1024 warps = exactly the 1024 (k, h, side) outputs.
__global__ void k_pre(const void* __restrict__ ei, const float* __restrict__ Wg,
                      const float* __restrict__ att_src, const float* __restrict__ att_dst) {
    int i = blockIdx.x * blockDim.x + threadIdx.x;
    if (i == 0) {
        const int2* p = (const int2*)ei;
        int ok64 = 1;
        for (int j = 0; j < 64; j++) if (p[j].y != 0) ok64 = 0;
        g_is64 = ok64;
    }
    if (i < Nn) g_cnt[i] = 0;
    if (i < Bb) { g_gstart[i] = Nn; g_gcnt[i] = 0; }
    int w = i >> 5, lane = i & 31;
    int k = w >> 4, h = (w >> 1) & 7, side = w & 1;
    const float* att = side ? att_dst : att_src;
    float2 wv = *(const float2*)(Wg + (size_t)k * HDD + h * D + 2 * lane);
    float2 av = *(const float2*)(att + h * D + 2 * lane);
    float s = wv.x * av.x + wv.y * av.y;
#pragma unroll
    for (int o = 16; o > 0; o >>= 1) s += __shfl_xor_sync(0xffffffff, s, o);
    if (lane == 0) {
        if (side) g_cd[h * D + k] = s;
        else      g_cs[h * D + k] = s;
    }
}

// ---------------- convert indices + dst histogram + graph segments --------------
__global__ void k_cvt_hist(const void* __restrict__ ei, const void* __restrict__ bat) {
    int i = blockIdx.x * blockDim.x + threadIdx.x;
    int is64 = g_is64;
    if (i < 2 * Ee) {
        int v = is64 ? (int)((const long long*)ei)[i] : ((const int*)ei)[i];
        g_eidx[i] = v;
        if (i >= Ee) atomicAdd(&g_cnt[v], 1);
    }
    if (i < Nn) {
        int b = is64 ? (int)((const long long*)bat)[i] : ((const int*)bat)[i];
        atomicMin(&g_gstart[b], i);
        atomicAdd(&g_gcnt[b], 1);
        atomicAdd(&g_cnt[i], 1);                        // self-loop
    }
}

// ---------------- h0 = relu(x@W0+b0);  a_s/a_d = h0 . c_s/c_d -------------------
__global__ void k_h0att(const float* __restrict__ x, const float* __restrict__ W0,
                        const float* __restrict__ b0) {
    __shared__ float sx[16 * IN_F];
    __shared__ float sW[IN_F * D];
    __shared__ float sh[16][65];
    int tid = threadIdx.x;  // 256
    int r0 = blockIdx.x * 16;
    for (int i = tid; i < 16 * IN_F; i += 256) sx[i] = x[r0 * IN_F + i];
    for (int i = tid; i < IN_F * D; i += 256) sW[i] = W0[i];
    __syncthreads();
    for (int i = tid; i < 1024; i += 256) {
        int r = i >> 6, c = i & 63;
        float a = b0[c];
#pragma unroll
        for (int k = 0; k < IN_F; k++) a = fmaf(sx[r * IN_F + k], sW[k * D + c], a);
        sh[r][c] = fmaxf(a, 0.f);
    }
    __syncthreads();
    {
        int r = tid >> 4, q = tid & 15;
        float4 v = make_float4(sh[r][q * 4], sh[r][q * 4 + 1], sh[r][q * 4 + 2], sh[r][q * 4 + 3]);
        *(float4*)(g_h0 + (size_t)(r0 + r) * D + q * 4) = v;
    }
    {
        int r = tid >> 4, hs = tid & 15, h = hs >> 1;
        const float* cv = (hs & 1) ? g_cd : g_cs;
        float a = 0.f;
#pragma unroll 8
        for (int k = 0; k < D; k++) a = fmaf(sh[r][k], cv[h * D + k], a);
        if (hs & 1) g_ad[(r0 + r) * HD + h] = a;
        else        g_as[(r0 + r) * HD + h] = a;
    }
}

// ---------------- single-block scan, vectorized loads ---------------------------
__global__ void k_scan() {
    __shared__ int warpsum[32];
    int tid = threadIdx.x;  // 1024; threads 0..999 own 20 elements each
    int v[20];
    int tot = 0;
    if (tid < 1000) {
        const int4* p4 = (const int4*)(g_cnt + tid * 20);
#pragma unroll
        for (int q = 0; q < 5; q++) {
            int4 t = p4[q];
            v[4 * q + 0] = tot; tot += t.x;
            v[4 * q + 1] = tot; tot += t.y;
            v[4 * q + 2] = tot; tot += t.z;
            v[4 * q + 3] = tot; tot += t.w;
        }
    }
    int lane = tid & 31, wid = tid >> 5;
    int sc = tot;
#pragma unroll
    for (int o = 1; o < 32; o <<= 1) {
        int t = __shfl_up_sync(0xffffffff, sc, o);
        if (lane >= o) sc += t;
    }
    if (lane == 31) warpsum[wid] = sc;
    __syncthreads();
    if (wid == 0) {
        int s = warpsum[lane];
#pragma unroll
        for (int o = 1; o < 32; o <<= 1) {
            int t = __shfl_up_sync(0xffffffff, s, o);
            if (lane >= o) s += t;
        }
        warpsum[lane] = s;
    }
    __syncthreads();
    int basesum = sc - tot + (wid ? warpsum[wid - 1] : 0);
    if (tid < 1000) {
#pragma unroll
        for (int i = 0; i < 20; i++) {
            int e = basesum + v[i];
            g_off[tid * 20 + i] = e;
            g_cur[tid * 20 + i] = e;
        }
    }
    if (tid == 999) g_off[Nn] = basesum + tot;
}

__global__ void k_scatter() {
    int e = blockIdx.x * blockDim.x + threadIdx.x;
    if (e >= ET) return;
    int src, dst;
    if (e < Ee) { src = g_eidx[e]; dst = g_eidx[Ee + e]; }
    else        { src = e - Ee;    dst = src; }
    int p = atomicAdd(&g_cur[dst], 1);
    g_esrc[p] = src;
}

// ---------------- fused segment softmax + h0 aggregation (single pass) ----------
// softmax max-subtraction dropped: logits are O(+-6), exp is fp32-safe, and
// softmax is shift-invariant so the result is identical.
__global__ void k_agg() {
    int warp = (blockIdx.x * blockDim.x + threadIdx.x) >> 5;
    int lane = threadIdx.x & 31;
    if (warp >= Nn) return;
    int v = warp;
    int beg = g_off[v], end = g_off[v + 1];
    float adh = (lane < 8) ? g_ad[v * HD + lane] : 0.f;

    float ssum = 0.f;
    float2 acc[8];
#pragma unroll
    for (int h = 0; h < 8; h++) acc[h] = make_float2(0.f, 0.f);
    for (int i = beg; i < end; i++) {
        int s = g_esrc[i];
        float w = 0.f;
        if (lane < 8) {
            float e = g_as[s * HD + lane] + adh;
            e = (e > 0.f) ? e : 0.2f * e;
            w = __expf(e);
            ssum += w;
        }
        float2 hp = *((const float2*)(g_h0 + (size_t)s * D) + lane);
#pragma unroll
        for (int h = 0; h < 8; h++) {
            float wh = __shfl_sync(0xffffffff, w, h);
            acc[h].x = fmaf(wh, hp.x, acc[h].x);
            acc[h].y = fmaf(wh, hp.y, acc[h].y);
        }
    }
    float invl = (lane < 8) ? 1.f / ssum : 0.f;
#pragma unroll
    for (int h = 0; h < 8; h++) {
        float iv = __shfl_sync(0xffffffff, invl, h);
        *((float2*)(g_p + (size_t)v * HDD + h * D) + lane) =
            make_float2(acc[h].x * iv, acc[h].y * iv);
    }
}

// ---------------- fused 2-GEMM: t=relu(p@bd(Wg)+bg); out=relu(t@Wh+bh) ----------
// f32x2 row-pair packing; activations transposed in shared [k][row], pad 20.
__global__ void k_big(const float* __restrict__ Wg, const float* __restrict__ bg,
                      const float* __restrict__ Wh, const float* __restrict__ bh) {
    __shared__ __align__(16) float sp[512 * 20];  // 40 KB
    int tid = threadIdx.x;  // 256
    int r0 = blockIdx.x * 16;
    // stage transposed (conflict-free: lanes write consecutive r)
#pragma unroll
    for (int it = 0; it < 8; it++) {
        int f = it * 256 + tid;
        int k4 = f >> 4, r = f & 15;
        float4 v = *(const float4*)(g_p + (size_t)(r0 + r) * HDD + 4 * k4);
        sp[(4 * k4 + 0) * 20 + r] = v.x;
        sp[(4 * k4 + 1) * 20 + r] = v.y;
        sp[(4 * k4 + 2) * 20 + r] = v.z;
        sp[(4 * k4 + 3) * 20 + r] = v.w;
    }
    __syncthreads();
    // phase 1: per-head 64x64, thread owns cols c0=tid, c1=tid+256
    int c0 = tid, c1 = tid + 256;
    int h0b = (c0 >> 6) << 6, h1b = (c1 >> 6) << 6;
    unsigned long long acc0[8], acc1[8];
#pragma unroll
    for (int q = 0; q < 8; q++) { acc0[q] = 0ULL; acc1[q] = 0ULL; }
#pragma unroll 2
    for (int kk = 0; kk < 64; kk++) {
        float w = Wg[(size_t)kk * HDD + c0];
        unsigned long long wp = pk2(w, w);
        const ulonglong2* row = (const ulonglong2*)(sp + (h0b + kk) * 20);
#pragma unroll
        for (int q = 0; q < 4; q++) {
            ulonglong2 av = row[q];
            fma2(acc0[2 * q], av.x, wp);
            fma2(acc0[2 * q + 1], av.y, wp);
        }
    }
#pragma unroll 2
    for (int kk = 0; kk < 64; kk++) {
        float w = Wg[(size_t)kk * HDD + c1];
        unsigned long long wp = pk2(w, w);
        const ulonglong2* row = (const ulonglong2*)(sp + (h1b + kk) * 20);
#pragma unroll
        for (int q = 0; q < 4; q++) {
            ulonglong2 av = row[q];
            fma2(acc1[2 * q], av.x, wp);
            fma2(acc1[2 * q + 1], av.y, wp);
        }
    }
    float bg0 = bg[c0], bg1 = bg[c1];
    __syncthreads();  // all reads of p done
#pragma unroll
    for (int q = 0; q < 8; q++) {
        float f0, f1;
        upk2(acc0[q], f0, f1);
        *(float2*)(sp + c0 * 20 + 2 * q) =
            make_float2(fmaxf(f0 + bg0, 0.f), fmaxf(f1 + bg0, 0.f));
        upk2(acc1[q], f0, f1);
        *(float2*)(sp + c1 * 20 + 2 * q) =
            make_float2(fmaxf(f0 + bg1, 0.f), fmaxf(f1 + bg1, 0.f));
    }
    __syncthreads();
    // phase 2: dense 512 -> 64; thread = (col c2, rows 4*rq..4*rq+3)
    int c2 = tid & 63, rq = tid >> 6;
    unsigned long long b0a = 0ULL, b1a = 0ULL, b0b = 0ULL, b1b = 0ULL;
#pragma unroll 4
    for (int j = 0; j < 512; j += 2) {
        float w = Wh[(size_t)j * D + c2];
        unsigned long long wp = pk2(w, w);
        ulonglong2 av = *(const ulonglong2*)(sp + j * 20 + 4 * rq);
        fma2(b0a, av.x, wp);
        fma2(b1a, av.y, wp);
        float w2 = Wh[(size_t)(j + 1) * D + c2];
        unsigned long long wp2 = pk2(w2, w2);
        ulonglong2 av2 = *(const ulonglong2*)(sp + (j + 1) * 20 + 4 * rq);
        fma2(b0b, av2.x, wp2);
        fma2(b1b, av2.y, wp2);
    }
    float bhc = bh[c2];
    float f0, f1, f2, f3, g0, g1, g2, g3;
    upk2(b0a, f0, f1); upk2(b1a, f2, f3);
    upk2(b0b, g0, g1); upk2(b1b, g2, g3);
    size_t ob = (size_t)(r0 + 4 * rq) * D + c2;
    g_outF[ob]         = fmaxf(f0 + g0 + bhc, 0.f);
    g_outF[ob + D]     = fmaxf(f1 + g1 + bhc, 0.f);
    g_outF[ob + 2 * D] = fmaxf(f2 + g2 + bhc, 0.f);
    g_outF[ob + 3 * D] = fmaxf(f3 + g3 + bhc, 0.f);
}

// ---------------- fully fused Set2Set (3 iters) + final MLP ---------------------
__global__ void k_s2s(const float* __restrict__ W_ih, const float* __restrict__ W_hh,
                      const float* __restrict__ b_ih, const float* __restrict__ b_hh,
                      const float* __restrict__ W1, const float* __restrict__ b1,
                      const float* __restrict__ W2, const float* __restrict__ b2,
                      float* __restrict__ out) {
    __shared__ __align__(16) float sqs[2 * D];
    __shared__ __align__(16) float shh[D], scc[D], sq[D], sg[4 * D];
    __shared__ float red[256];
    int b = blockIdx.x, tid = threadIdx.x;  // 256
    if (tid < 2 * D) sqs[tid] = 0.f;
    if (tid < D) { shh[tid] = 0.f; scc[tid] = 0.f; }
    int start = g_gstart[b], cnt = g_gcnt[b];
    __syncthreads();
    for (int it = 0; it < 3; it++) {
        float acc = b_ih[tid] + b_hh[tid];
        const float4* wi = (const float4*)(W_ih + tid * 2 * D);
#pragma unroll
        for (int k = 0; k < 2 * D / 4; k++) {
            float4 w = wi[k];
            acc += w.x * sqs[4 * k] + w.y * sqs[4 * k + 1] + w.z * sqs[4 * k + 2] + w.w * sqs[4 * k + 3];
        }
        const float4* wh = (const float4*)(W_hh + tid * D);
#pragma unroll
        for (int k = 0; k < D / 4; k++) {
            float4 w = wh[k];
            acc += w.x * shh[4 * k] + w.y * shh[4 * k + 1] + w.z * shh[4 * k + 2] + w.w * shh[4 * k + 3];
        }
        sg[tid] = acc;
        __syncthreads();
        if (tid < D) {
            float ig = sg[tid], fg = sg[D + tid], gg = sg[2 * D + tid], og = sg[3 * D + tid];
            float c = sigf(fg) * scc[tid] + sigf(ig) * tanhf(gg);
            float hv = sigf(og) * tanhf(c);
            scc[tid] = c; shh[tid] = hv; sq[tid] = hv;
        }
        __syncthreads();
        float lm = -3.0e38f;
        const float4* q4 = (const float4*)sq;
        for (int i = tid; i < cnt; i += 256) {
            int n = start + i;
            const float4* orow = (const float4*)(g_outF + (size_t)n * D);
            float e = 0.f;
#pragma unroll
            for (int j = 0; j < 16; j++) {
                float4 o = orow[j], qv = q4[j];
                e += o.x * qv.x + o.y * qv.y + o.z * qv.z + o.w * qv.w;
            }
            g_w2[n] = e;
            lm = fmaxf(lm, e);
        }
        red[tid] = lm;
        __syncthreads();
        for (int o = 128; o > 0; o >>= 1) {
            if (tid < o) red[tid] = fmaxf(red[tid], red[tid + o]);
            __syncthreads();
        }
        float m2 = red[0];
        __syncthreads();
        float ls = 0.f;
        for (int i = tid; i < cnt; i += 256) {
            int n = start + i;
            float w = __expf(g_w2[n] - m2);
            g_w2[n] = w;
            ls += w;
        }
        red[tid] = ls;
        __syncthreads();
        for (int o = 128; o > 0; o >>= 1) {
            if (tid < o) red[tid] += red[tid + o];
            __syncthreads();
        }
        float s2 = red[0];
        __syncthreads();
        int c = tid & 63, g = tid >> 6;
        float racc = 0.f;
        for (int i = g; i < cnt; i += 4) {
            int n = start + i;
            racc += g_w2[n] * g_outF[(size_t)n * D + c];
        }
        red[tid] = racc;
        __syncthreads();
        if (tid < 64) {
            float r = red[tid] + red[64 + tid] + red[128 + tid] + red[192 + tid];
            sqs[D + tid] = (cnt > 0) ? r / s2 : 0.f;
            sqs[tid] = sq[tid];
        }
        __syncthreads();
    }
    if (tid < D) {
        float acc = b1[tid];
        for (int k = 0; k < 2 * D; k++) acc = fmaf(sqs[k], W1[k * D + tid], acc);
        red[tid] = fmaxf(acc, 0.f) * W2[tid];
    }
    __syncthreads();
    if (tid < 32) red[tid] += red[tid + 32];
    __syncthreads();
    if (tid < 16) red[tid] += red[tid + 16];
    __syncthreads();
    if (tid < 8) red[tid] += red[tid + 8];
    __syncthreads();
    if (tid < 4) red[tid] += red[tid + 4];
    __syncthreads();
    if (tid < 2) red[tid] += red[tid + 2];
    __syncthreads();
    if (tid == 0) out[b] = red[0] + red[1] + b2[0];
}

// ---------------- launch --------------------------------------------------------
extern "C" void kernel_launch(void* const* d_in, const int* in_sizes, int n_in,
                              void* d_out, int out_size) {
    const float* x        = (const float*)d_in[0];
    const void*  ei       = d_in[1];
    const void*  bat      = d_in[2];
    const float* W0       = (const float*)d_in[3];
    const float* b0       = (const float*)d_in[4];
    const float* Wg       = (const float*)d_in[5];
    const float* att_src  = (const float*)d_in[6];
    const float* att_dst  = (const float*)d_in[7];
    const float* bg       = (const float*)d_in[8];
    const float* Wh       = (const float*)d_in[9];
    const float* bh       = (const float*)d_in[10];
    const float* W_ih     = (const float*)d_in[11];
    const float* W_hh     = (const float*)d_in[12];
    const float* b_ih     = (const float*)d_in[13];
    const float* b_hh     = (const float*)d_in[14];
    const float* W1       = (const float*)d_in[15];
    const float* b1       = (const float*)d_in[16];
    const float* W2       = (const float*)d_in[17];
    const float* b2       = (const float*)d_in[18];
    float* out            = (float*)d_out;

    k_pre<<<128, 256>>>(ei, Wg, att_src, att_dst);
    k_cvt_hist<<<(2 * Ee + 255) / 256, 256>>>(ei, bat);
    k_h0att<<<Nn / 16, 256>>>(x, W0, b0);
    k_scan<<<1, 1024>>>();
    k_scatter<<<(ET + 255) / 256, 256>>>();
    k_agg<<<(Nn * 32 + 255) / 256, 256>>>();
    k_big<<<Nn / 16, 256>>>(Wg, bg, Wh, bh);
    k_s2s<<<Bb, 256>>>(W_ih, W_hh, b_ih, b_hh, W1, b1, W2, b2, out);
}

// round 14
// speedup vs baseline: 2.0393x; 1.0873x over previous
#include <cuda_runtime.h>
#include <math.h>

#define Nn 20000
#define Ee 320000
#define ET (Ee + Nn)
#define Bb 128
#define IN_F 25
#define D 64
#define HD 8
#define HDD (HD * D) /* 512 */
#define TCAP 256     /* s2s shared tile capacity (rows) */

// ---------------- scratch (static device globals; no allocation) ----------------
__device__ float g_h0[Nn * D];          // 5.1 MB (L2-resident)
__device__ float g_as[Nn * HD];
__device__ float g_ad[Nn * HD];
__device__ float g_cs[HD * D];
__device__ float g_cd[HD * D];
__device__ int   g_cnt[Nn];
__device__ int   g_off[Nn + 1];
__device__ int   g_cur[Nn];
__device__ int   g_esrc[ET];
__device__ float g_p[Nn * HDD];         // aggregated h0 per head, 41 MB
__device__ float g_outF[Nn * D];        // 5.1 MB
__device__ int   g_gstart[Bb];
__device__ int   g_gcnt[Bb];
__device__ float g_w2[Nn];
__device__ int   g_is64;
__device__ int   g_bsum[32];
__device__ int   g_bflag[32];

__device__ __forceinline__ float sigf(float x) { return 1.0f / (1.0f + __expf(-x)); }

// ---- packed fp32x2 helpers ----
__device__ __forceinline__ unsigned long long pk2(float lo, float hi) {
    unsigned long long r;
    asm("mov.b64 %0, {%1,%2};" : "=l"(r) : "f"(lo), "f"(hi));
    return r;
}
__device__ __forceinline__ void upk2(unsigned long long v, float& lo, float& hi) {
    asm("mov.b64 {%0,%1}, %2;" : "=f"(lo), "=f"(hi) : "l"(v));
}
__device__ __forceinline__ void fma2(unsigned long long& acc, unsigned long long a,
                                     unsigned long long b) {
    asm("fma.rn.f32x2 %0, %1, %2, %0;" : "+l"(acc) : "l"(a), "l"(b));
}

// ---------------- fused prologue: detect dtype + init + c_s/c_d -----------------
__global__ void k_pre(const void* __restrict__ ei, const float* __restrict__ Wg,
                      const float* __restrict__ att_src, const float* __restrict__ att_dst) {
    int i = blockIdx.x * blockDim.x + threadIdx.x;
    if (i == 0) {
        const int2* p = (const int2*)ei;
        int ok64 = 1;
        for (int j = 0; j < 64; j++) if (p[j].y != 0) ok64 = 0;
        g_is64 = ok64;
    }
    if (i < Nn) g_cnt[i] = 0;
    if (i < Bb) { g_gstart[i] = Nn; g_gcnt[i] = 0; }
    if (i < 32) { g_bflag[i] = 0; g_bsum[i] = 0; }
    int w = i >> 5, lane = i & 31;
    int k = w >> 4, h = (w >> 1) & 7, side = w & 1;
    const float* att = side ? att_dst : att_src;
    float2 wv = *(const float2*)(Wg + (size_t)k * HDD + h * D + 2 * lane);
    float2 av = *(const float2*)(att + h * D + 2 * lane);
    float s = wv.x * av.x + wv.y * av.y;
#pragma unroll
    for (int o = 16; o > 0; o >>= 1) s += __shfl_xor_sync(0xffffffff, s, o);
    if (lane == 0) {
        if (side) g_cd[h * D + k] = s;
        else      g_cs[h * D + k] = s;
    }
}

// ---------------- dst histogram + graph segments (no index copy) ----------------
__global__ void k_hist(const void* __restrict__ ei, const void* __restrict__ bat) {
    int i = blockIdx.x * blockDim.x + threadIdx.x;
    int is64 = g_is64;
    if (i < Ee) {
        int d = is64 ? (int)((const long long*)ei)[Ee + i] : ((const int*)ei)[Ee + i];
        atomicAdd(&g_cnt[d], 1);
    }
    if (i < Nn) {
        int b = is64 ? (int)((const long long*)bat)[i] : ((const int*)bat)[i];
        atomicMin(&g_gstart[b], i);
        atomicAdd(&g_gcnt[b], 1);
        atomicAdd(&g_cnt[i], 1);                        // self-loop
    }
}

// ---------------- h0 = relu(x@W0+b0);  a_s/a_d = h0 . c_s/c_d -------------------
__global__ void k_h0att(const float* __restrict__ x, const float* __restrict__ W0,
                        const float* __restrict__ b0) {
    __shared__ float sx[16 * IN_F];
    __shared__ float sW[IN_F * D];
    __shared__ float sh[16][65];
    int tid = threadIdx.x;  // 256
    int r0 = blockIdx.x * 16;
    for (int i = tid; i < 16 * IN_F; i += 256) sx[i] = x[r0 * IN_F + i];
    for (int i = tid; i < IN_F * D; i += 256) sW[i] = W0[i];
    __syncthreads();
    for (int i = tid; i < 1024; i += 256) {
        int r = i >> 6, c = i & 63;
        float a = b0[c];
#pragma unroll
        for (int k = 0; k < IN_F; k++) a = fmaf(sx[r * IN_F + k], sW[k * D + c], a);
        sh[r][c] = fmaxf(a, 0.f);
    }
    __syncthreads();
    {
        int r = tid >> 4, q = tid & 15;
        float4 v = make_float4(sh[r][q * 4], sh[r][q * 4 + 1], sh[r][q * 4 + 2], sh[r][q * 4 + 3]);
        *(float4*)(g_h0 + (size_t)(r0 + r) * D + q * 4) = v;
    }
    {
        int r = tid >> 4, hs = tid & 15, h = hs >> 1;
        const float* cv = (hs & 1) ? g_cd : g_cs;
        float a = 0.f;
#pragma unroll 8
        for (int k = 0; k < D; k++) a = fmaf(sh[r][k], cv[h * D + k], a);
        if (hs & 1) g_ad[(r0 + r) * HD + h] = a;
        else        g_as[(r0 + r) * HD + h] = a;
    }
}

// ---------------- decoupled-lookback scan: grid 20 x 1024 -----------------------
__global__ void k_scan() {
    __shared__ int ws[32];
    __shared__ int s_base;
    int b = blockIdx.x, tid = threadIdx.x;
    int idx = b * 1000 + tid;
    int v = (tid < 1000) ? g_cnt[idx] : 0;
    int lane = tid & 31, wid = tid >> 5;
    int sc = v;
#pragma unroll
    for (int o = 1; o < 32; o <<= 1) {
        int t = __shfl_up_sync(0xffffffff, sc, o);
        if (lane >= o) sc += t;
    }
    if (lane == 31) ws[wid] = sc;
    __syncthreads();
    if (wid == 0) {
        int s = ws[lane];
#pragma unroll
        for (int o = 1; o < 32; o <<= 1) {
            int t = __shfl_up_sync(0xffffffff, s, o);
            if (lane >= o) s += t;
        }
        ws[lane] = s;
    }
    __syncthreads();
    int incl = sc + (wid ? ws[wid - 1] : 0);
    // publish block aggregate
    if (tid == 0) {
        int total = ws[31];
        g_bsum[b] = total;
        __threadfence();
        atomicExch(&g_bflag[b], 1);
    }
    // lookback (warp 0): sum aggregates of blocks 0..b-1
    if (wid == 0) {
        int contrib = 0;
        if (lane < b) {
            while (atomicAdd(&g_bflag[lane], 0) == 0) {}
            contrib = atomicAdd(&g_bsum[lane], 0);
        }
#pragma unroll
        for (int o = 16; o > 0; o >>= 1) contrib += __shfl_xor_sync(0xffffffff, contrib, o);
        if (lane == 0) s_base = contrib;
    }
    __syncthreads();
    int ex = s_base + incl - v;
    if (tid < 1000) {
        g_off[idx] = ex;
        g_cur[idx] = ex;
    }
    if (b == 19 && tid == 999) g_off[Nn] = s_base + incl;
}

// ---------------- scatter (reads edge_index directly) ---------------------------
__global__ void k_scatter(const void* __restrict__ ei) {
    int e = blockIdx.x * blockDim.x + threadIdx.x;
    if (e >= ET) return;
    int src, dst;
    if (e < Ee) {
        if (g_is64) {
            src = (int)((const long long*)ei)[e];
            dst = (int)((const long long*)ei)[Ee + e];
        } else {
            src = ((const int*)ei)[e];
            dst = ((const int*)ei)[Ee + e];
        }
    } else { src = e - Ee; dst = src; }
    int p = atomicAdd(&g_cur[dst], 1);
    g_esrc[p] = src;
}

// ---------------- fused segment softmax + h0 aggregation (single pass) ----------
__global__ void k_agg() {
    int warp = (blockIdx.x * blockDim.x + threadIdx.x) >> 5;
    int lane = threadIdx.x & 31;
    if (warp >= Nn) return;
    int v = warp;
    int beg = g_off[v], end = g_off[v + 1];
    float adh = (lane < 8) ? g_ad[v * HD + lane] : 0.f;

    float ssum = 0.f;
    float2 acc[8];
#pragma unroll
    for (int h = 0; h < 8; h++) acc[h] = make_float2(0.f, 0.f);
    for (int i = beg; i < end; i++) {
        int s = g_esrc[i];
        float w = 0.f;
        if (lane < 8) {
            float e = g_as[s * HD + lane] + adh;
            e = (e > 0.f) ? e : 0.2f * e;
            w = __expf(e);
            ssum += w;
        }
        float2 hp = *((const float2*)(g_h0 + (size_t)s * D) + lane);
#pragma unroll
        for (int h = 0; h < 8; h++) {
            float wh = __shfl_sync(0xffffffff, w, h);
            acc[h].x = fmaf(wh, hp.x, acc[h].x);
            acc[h].y = fmaf(wh, hp.y, acc[h].y);
        }
    }
    float invl = (lane < 8) ? 1.f / ssum : 0.f;
#pragma unroll
    for (int h = 0; h < 8; h++) {
        float iv = __shfl_sync(0xffffffff, invl, h);
        *((float2*)(g_p + (size_t)v * HDD + h * D) + lane) =
            make_float2(acc[h].x * iv, acc[h].y * iv);
    }
}

// ---------------- fused 2-GEMM: t=relu(p@bd(Wg)+bg); out=relu(t@Wh+bh) ----------
__global__ void k_big(const float* __restrict__ Wg, const float* __restrict__ bg,
                      const float* __restrict__ Wh, const float* __restrict__ bh) {
    __shared__ __align__(16) float sp[512 * 20];  // 40 KB
    int tid = threadIdx.x;  // 256
    int r0 = blockIdx.x * 16;
#pragma unroll
    for (int it = 0; it < 8; it++) {
        int f = it * 256 + tid;
        int k4 = f >> 4, r = f & 15;
        float4 v = *(const float4*)(g_p + (size_t)(r0 + r) * HDD + 4 * k4);
        sp[(4 * k4 + 0) * 20 + r] = v.x;
        sp[(4 * k4 + 1) * 20 + r] = v.y;
        sp[(4 * k4 + 2) * 20 + r] = v.z;
        sp[(4 * k4 + 3) * 20 + r] = v.w;
    }
    __syncthreads();
    int c0 = tid, c1 = tid + 256;
    int h0b = (c0 >> 6) << 6, h1b = (c1 >> 6) << 6;
    unsigned long long acc0[8], acc1[8];
#pragma unroll
    for (int q = 0; q < 8; q++) { acc0[q] = 0ULL; acc1[q] = 0ULL; }
#pragma unroll 2
    for (int kk = 0; kk < 64; kk++) {
        float w = Wg[(size_t)kk * HDD + c0];
        unsigned long long wp = pk2(w, w);
        const ulonglong2* row = (const ulonglong2*)(sp + (h0b + kk) * 20);
#pragma unroll
        for (int q = 0; q < 4; q++) {
            ulonglong2 av = row[q];
            fma2(acc0[2 * q], av.x, wp);
            fma2(acc0[2 * q + 1], av.y, wp);
        }
    }
#pragma unroll 2
    for (int kk = 0; kk < 64; kk++) {
        float w = Wg[(size_t)kk * HDD + c1];
        unsigned long long wp = pk2(w, w);
        const ulonglong2* row = (const ulonglong2*)(sp + (h1b + kk) * 20);
#pragma unroll
        for (int q = 0; q < 4; q++) {
            ulonglong2 av = row[q];
            fma2(acc1[2 * q], av.x, wp);
            fma2(acc1[2 * q + 1], av.y, wp);
        }
    }
    float bg0 = bg[c0], bg1 = bg[c1];
    __syncthreads();
#pragma unroll
    for (int q = 0; q < 8; q++) {
        float f0, f1;
        upk2(acc0[q], f0, f1);
        *(float2*)(sp + c0 * 20 + 2 * q) =
            make_float2(fmaxf(f0 + bg0, 0.f), fmaxf(f1 + bg0, 0.f));
        upk2(acc1[q], f0, f1);
        *(float2*)(sp + c1 * 20 + 2 * q) =
            make_float2(fmaxf(f0 + bg1, 0.f), fmaxf(f1 + bg1, 0.f));
    }
    __syncthreads();
    int c2 = tid & 63, rq = tid >> 6;
    unsigned long long b0a = 0ULL, b1a = 0ULL, b0b = 0ULL, b1b = 0ULL;
#pragma unroll 4
    for (int j = 0; j < 512; j += 2) {
        float w = Wh[(size_t)j * D + c2];
        unsigned long long wp = pk2(w, w);
        ulonglong2 av = *(const ulonglong2*)(sp + j * 20 + 4 * rq);
        fma2(b0a, av.x, wp);
        fma2(b1a, av.y, wp);
        float w2 = Wh[(size_t)(j + 1) * D + c2];
        unsigned long long wp2 = pk2(w2, w2);
        ulonglong2 av2 = *(const ulonglong2*)(sp + (j + 1) * 20 + 4 * rq);
        fma2(b0b, av2.x, wp2);
        fma2(b1b, av2.y, wp2);
    }
    float bhc = bh[c2];
    float f0, f1, f2, f3, g0, g1, g2, g3;
    upk2(b0a, f0, f1); upk2(b1a, f2, f3);
    upk2(b0b, g0, g1); upk2(b1b, g2, g3);
    size_t ob = (size_t)(r0 + 4 * rq) * D + c2;
    g_outF[ob]         = fmaxf(f0 + g0 + bhc, 0.f);
    g_outF[ob + D]     = fmaxf(f1 + g1 + bhc, 0.f);
    g_outF[ob + 2 * D] = fmaxf(f2 + g2 + bhc, 0.f);
    g_outF[ob + 3 * D] = fmaxf(f3 + g3 + bhc, 0.f);
}

// ---------------- fully fused Set2Set (3 iters) + final MLP ---------------------
// Graph's outF tile cached in dynamic shared (cnt <= TCAP fast path; global
// fallback with identical indexing via pointer select).
__global__ void k_s2s(const float* __restrict__ W_ih, const float* __restrict__ W_hh,
                      const float* __restrict__ b_ih, const float* __restrict__ b_hh,
                      const float* __restrict__ W1, const float* __restrict__ b1,
                      const float* __restrict__ W2, const float* __restrict__ b2,
                      float* __restrict__ out) {
    extern __shared__ __align__(16) float st[];   // TCAP * 64
    __shared__ __align__(16) float sqs[2 * D];
    __shared__ __align__(16) float shh[D], scc[D], sq[D], sg[4 * D];
    __shared__ float se[TCAP];
    __shared__ float red[256];
    int b = blockIdx.x, tid = threadIdx.x;  // 256
    if (tid < 2 * D) sqs[tid] = 0.f;
    if (tid < D) { shh[tid] = 0.f; scc[tid] = 0.f; }
    int start = g_gstart[b], cnt = g_gcnt[b];
    bool fast = (cnt <= TCAP);
    const float* baseF;
    float* sw;
    if (fast) {
        const float4* gsrc = (const float4*)(g_outF + (size_t)start * D);
        float4* gdst = (float4*)st;
        for (int i = tid; i < cnt * 16; i += 256) gdst[i] = gsrc[i];
        baseF = st;
        sw = se;
    } else {
        baseF = g_outF + (size_t)start * D;
        sw = g_w2 + start;
    }
    __syncthreads();
    for (int it = 0; it < 3; it++) {
        float acc = b_ih[tid] + b_hh[tid];
        const float4* wi = (const float4*)(W_ih + tid * 2 * D);
#pragma unroll
        for (int k = 0; k < 2 * D / 4; k++) {
            float4 w = wi[k];
            acc += w.x * sqs[4 * k] + w.y * sqs[4 * k + 1] + w.z * sqs[4 * k + 2] + w.w * sqs[4 * k + 3];
        }
        const float4* wh = (const float4*)(W_hh + tid * D);
#pragma unroll
        for (int k = 0; k < D / 4; k++) {
            float4 w = wh[k];
            acc += w.x * shh[4 * k] + w.y * shh[4 * k + 1] + w.z * shh[4 * k + 2] + w.w * shh[4 * k + 3];
        }
        sg[tid] = acc;
        __syncthreads();
        if (tid < D) {
            float ig = sg[tid], fg = sg[D + tid], gg = sg[2 * D + tid], og = sg[3 * D + tid];
            float c = sigf(fg) * scc[tid] + sigf(ig) * tanhf(gg);
            float hv = sigf(og) * tanhf(c);
            scc[tid] = c; shh[tid] = hv; sq[tid] = hv;
        }
        __syncthreads();
        float lm = -3.0e38f;
        const float4* q4 = (const float4*)sq;
        for (int i = tid; i < cnt; i += 256) {
            const float4* orow = (const float4*)(baseF + (size_t)i * D);
            float e = 0.f;
#pragma unroll
            for (int j = 0; j < 16; j++) {
                float4 o = orow[j], qv = q4[j];
                e += o.x * qv.x + o.y * qv.y + o.z * qv.z + o.w * qv.w;
            }
            sw[i] = e;
            lm = fmaxf(lm, e);
        }
        red[tid] = lm;
        __syncthreads();
        for (int o = 128; o > 0; o >>= 1) {
            if (tid < o) red[tid] = fmaxf(red[tid], red[tid + o]);
            __syncthreads();
        }
        float m2 = red[0];
        __syncthreads();
        float ls = 0.f;
        for (int i = tid; i < cnt; i += 256) {
            float w = __expf(sw[i] - m2);
            sw[i] = w;
            ls += w;
        }
        red[tid] = ls;
        __syncthreads();
        for (int o = 128; o > 0; o >>= 1) {
            if (tid < o) red[tid] += red[tid + o];
            __syncthreads();
        }
        float s2 = red[0];
        __syncthreads();
        int c = tid & 63, g = tid >> 6;
        float racc = 0.f;
        for (int i = g; i < cnt; i += 4)
            racc += sw[i] * baseF[(size_t)i * D + c];
        red[tid] = racc;
        __syncthreads();
        if (tid < 64) {
            float r = red[tid] + red[64 + tid] + red[128 + tid] + red[192 + tid];
            sqs[D + tid] = (cnt > 0) ? r / s2 : 0.f;
            sqs[tid] = sq[tid];
        }
        __syncthreads();
    }
    if (tid < D) {
        float acc = b1[tid];
        for (int k = 0; k < 2 * D; k++) acc = fmaf(sqs[k], W1[k * D + tid], acc);
        red[tid] = fmaxf(acc, 0.f) * W2[tid];
    }
    __syncthreads();
    if (tid < 32) red[tid] += red[tid + 32];
    __syncthreads();
    if (tid < 16) red[tid] += red[tid + 16];
    __syncthreads();
    if (tid < 8) red[tid] += red[tid + 8];
    __syncthreads();
    if (tid < 4) red[tid] += red[tid + 4];
    __syncthreads();
    if (tid < 2) red[tid] += red[tid + 2];
    __syncthreads();
    if (tid == 0) out[b] = red[0] + red[1] + b2[0];
}

// ---------------- launch --------------------------------------------------------
extern "C" void kernel_launch(void* const* d_in, const int* in_sizes, int n_in,
                              void* d_out, int out_size) {
    const float* x        = (const float*)d_in[0];
    const void*  ei       = d_in[1];
    const void*  bat      = d_in[2];
    const float* W0       = (const float*)d_in[3];
    const float* b0       = (const float*)d_in[4];
    const float* Wg       = (const float*)d_in[5];
    const float* att_src  = (const float*)d_in[6];
    const float* att_dst  = (const float*)d_in[7];
    const float* bg       = (const float*)d_in[8];
    const float* Wh       = (const float*)d_in[9];
    const float* bh       = (const float*)d_in[10];
    const float* W_ih     = (const float*)d_in[11];
    const float* W_hh     = (const float*)d_in[12];
    const float* b_ih     = (const float*)d_in[13];
    const float* b_hh     = (const float*)d_in[14];
    const float* W1       = (const float*)d_in[15];
    const float* b1       = (const float*)d_in[16];
    const float* W2       = (const float*)d_in[17];
    const float* b2       = (const float*)d_in[18];
    float* out            = (float*)d_out;

    cudaFuncSetAttribute(k_s2s, cudaFuncAttributeMaxDynamicSharedMemorySize,
                         TCAP * D * (int)sizeof(float));

    k_pre<<<128, 256>>>(ei, Wg, att_src, att_dst);
    k_hist<<<(Ee + 255) / 256, 256>>>(ei, bat);
    k_h0att<<<Nn / 16, 256>>>(x, W0, b0);
    k_scan<<<20, 1024>>>();
    k_scatter<<<(ET + 255) / 256, 256>>>(ei);
    k_agg<<<(Nn * 32 + 255) / 256, 256>>>();
    k_big<<<Nn / 16, 256>>>(Wg, bg, Wh, bh);
    k_s2s<<<Bb, 256, TCAP * D * (int)sizeof(float)>>>(W_ih, W_hh, b_ih, b_hh,
                                                      W1, b1, W2, b2, out);
}